// round 1
// baseline (speedup 1.0000x reference)
#include <cuda_runtime.h>
#include <math.h>

#define DIMK 512
#define HD   1024
#define BB   64
#define VV   64

// Scratch (device globals: allocation-free)
__device__ __align__(16) float g_caus[VV * HD];   // embed @ Wc + b1   [i][h]
__device__ __align__(16) float g_eff [VV * HD];   // embed @ We        [j][h]
__device__ __align__(16) float g_ctxT[HD * BB];   // (state+action)@Wx, TRANSPOSED [h][b]

// ---------------------------------------------------------------------------
// Phase 1: three 64x512 @ 512x1024 GEMMs.
// grid = (32 col-tiles of 32, 3 slots). block = 256 threads.
// Each thread: 4 rows x 2 cols accumulators.
// ---------------------------------------------------------------------------
__global__ void __launch_bounds__(256) gemm_kernel(
    const float* __restrict__ state, const float* __restrict__ action,
    const float* __restrict__ embed, const float* __restrict__ W1,
    const float* __restrict__ b1)
{
    const int slot    = blockIdx.y;              // 0: cause, 1: effect, 2: ctx
    const int colbase = blockIdx.x * 32;
    const float* W = W1 + slot * DIMK * HD;      // row-block of W1

    __shared__ float Xs[64][132];                // padded: conflict-free, float4-aligned

    const int tid = threadIdx.x;
    const int tx  = tid & 15;                    // col-pair index (2 cols each)
    const int ty  = tid >> 4;                    // 0..15 row group

    float acc[4][2] = {};

    for (int kt = 0; kt < DIMK; kt += 128) {
        // Load X tile [64][128] (slot 2 fuses state+action)
        for (int lin = tid; lin < 64 * 32; lin += 256) {
            int row = lin >> 5;
            int q   = lin & 31;
            int gc  = kt + q * 4;
            float4 v;
            if (slot < 2) {
                v = *reinterpret_cast<const float4*>(embed + row * DIMK + gc);
            } else {
                float4 s4 = *reinterpret_cast<const float4*>(state  + row * DIMK + gc);
                float4 a4 = *reinterpret_cast<const float4*>(action + row * DIMK + gc);
                v = make_float4(s4.x + a4.x, s4.y + a4.y, s4.z + a4.z, s4.w + a4.w);
            }
            *reinterpret_cast<float4*>(&Xs[row][q * 4]) = v;
        }
        __syncthreads();

        #pragma unroll 4
        for (int k = 0; k < 128; k++) {
            float2 w = *reinterpret_cast<const float2*>(W + (kt + k) * HD + colbase + 2 * tx);
            #pragma unroll
            for (int r = 0; r < 4; r++) {
                float xv = Xs[ty + 16 * r][k];
                acc[r][0] = fmaf(xv, w.x, acc[r][0]);
                acc[r][1] = fmaf(xv, w.y, acc[r][1]);
            }
        }
        __syncthreads();
    }

    #pragma unroll
    for (int r = 0; r < 4; r++) {
        int row = ty + 16 * r;
        int c0  = colbase + 2 * tx;
        if (slot == 0) {
            g_caus[row * HD + c0]     = acc[r][0] + b1[c0];
            g_caus[row * HD + c0 + 1] = acc[r][1] + b1[c0 + 1];
        } else if (slot == 1) {
            g_eff[row * HD + c0]      = acc[r][0];
            g_eff[row * HD + c0 + 1]  = acc[r][1];
        } else {
            // transposed store: [h][b]
            g_ctxT[c0 * BB + row]       = acc[r][0];
            g_ctxT[(c0 + 1) * BB + row] = acc[r][1];
        }
    }
}

// exact GELU (matches jax.nn.gelu approximate=False)
__device__ __forceinline__ float gelu_exact(float x) {
    return 0.5f * x * (1.0f + erff(x * 0.70710678118654752f));
}

// ---------------------------------------------------------------------------
// Phase 2: scores[i,j] = mean_b sigmoid( sum_h gelu(ctx[b,h]+caus[i,h]+eff[j,h])*W2[h] + b2 )
// Block = 512 threads = 16 warps; each warp owns one (i,j) of a 4x4 tile.
// Each lane owns batches (2*lane, 2*lane+1) via float2 from transposed ctx.
// ctx staged through shared in 128-h tiles -> ctx read from L2 exactly once/block.
// ---------------------------------------------------------------------------
__global__ void __launch_bounds__(512) score_kernel(
    const float* __restrict__ W2, const float* __restrict__ b2,
    float* __restrict__ out)
{
    extern __shared__ float sm[];
    float* caus_s = sm;                 // 4*1024
    float* eff_s  = sm + 4 * 1024;      // 4*1024
    float* w2_s   = sm + 8 * 1024;      // 1024
    float* ctx_s  = sm + 9 * 1024;      // 128*64

    const int tid = threadIdx.x;
    const int i0  = (blockIdx.x >> 4) * 4;
    const int j0  = (blockIdx.x & 15) * 4;

    for (int lin = tid; lin < 4 * 1024; lin += 512) {
        int r = lin >> 10, c = lin & 1023;
        caus_s[lin] = g_caus[(i0 + r) * HD + c];
        eff_s[lin]  = g_eff [(j0 + r) * HD + c];
    }
    for (int lin = tid; lin < 1024; lin += 512) w2_s[lin] = W2[lin];

    const int w    = tid >> 5;
    const int lane = tid & 31;
    const int wi   = w >> 2, wj = w & 3;
    const float* cs = caus_s + wi * 1024;
    const float* es = eff_s  + wj * 1024;

    float acc0 = 0.f, acc1 = 0.f;

    for (int ht = 0; ht < HD; ht += 128) {
        __syncthreads();   // also covers caus/eff/w2 loads on first iter
        for (int lin = tid * 4; lin < 128 * 64; lin += 512 * 4) {
            *reinterpret_cast<float4*>(ctx_s + lin) =
                *reinterpret_cast<const float4*>(g_ctxT + ht * BB + lin);
        }
        __syncthreads();

        #pragma unroll 4
        for (int k = 0; k < 128; k++) {
            int h = ht + k;
            float ce = cs[h] + es[h];
            float wv = w2_s[h];
            float2 c = *reinterpret_cast<const float2*>(ctx_s + k * 64 + 2 * lane);
            acc0 = fmaf(gelu_exact(ce + c.x), wv, acc0);
            acc1 = fmaf(gelu_exact(ce + c.y), wv, acc1);
        }
    }

    float bb = b2[0];
    float s  = 1.0f / (1.0f + expf(-(acc0 + bb)))
             + 1.0f / (1.0f + expf(-(acc1 + bb)));
    #pragma unroll
    for (int off = 16; off; off >>= 1)
        s += __shfl_down_sync(0xffffffffu, s, off);
    if (lane == 0)
        out[(i0 + wi) * VV + (j0 + wj)] = s * (1.0f / 64.0f);
}

// ---------------------------------------------------------------------------
extern "C" void kernel_launch(void* const* d_in, const int* in_sizes, int n_in,
                              void* d_out, int out_size)
{
    const float* state  = (const float*)d_in[0];
    const float* action = (const float*)d_in[1];
    const float* embed  = (const float*)d_in[2];
    const float* W1     = (const float*)d_in[3];
    const float* b1     = (const float*)d_in[4];
    const float* W2     = (const float*)d_in[5];
    const float* b2     = (const float*)d_in[6];
    float* out = (float*)d_out;

    dim3 g1(32, 3);
    gemm_kernel<<<g1, 256>>>(state, action, embed, W1, b1);

    const int smem = (4 * 1024 + 4 * 1024 + 1024 + 128 * 64) * sizeof(float); // 69632 B
    cudaFuncSetAttribute(score_kernel, cudaFuncAttributeMaxDynamicSharedMemorySize, smem);
    score_kernel<<<256, 512, smem>>>(W2, b2, out);
}

// round 2
// speedup vs baseline: 2.2581x; 2.2581x over previous
#include <cuda_runtime.h>
#include <math.h>

#define DIMK 512
#define HD   1024

typedef unsigned long long ull;

// Scratch (device globals: allocation-free). k-split partial results.
__device__ __align__(16) float g_causA[64 * HD];
__device__ __align__(16) float g_causB[64 * HD];
__device__ __align__(16) float g_effA [64 * HD];
__device__ __align__(16) float g_effB [64 * HD];
__device__ __align__(16) float g_ctxT [HD * 64];   // transposed [h][b]

// ---------------------------------------------------------------------------
// Phase 1: three 64x512 @ 512x1024 GEMMs, k-split for slots 0/1.
// grid = (64, 3). Slots 0/1: x>>1 = col-tile (32 cols), x&1 = k-half (256).
// Slot 2 (ctx): x<32 = col-tile (32 cols), full k (2x work, only 32 blocks).
// block = 256 threads; each thread 4 rows x 2 cols.
// ---------------------------------------------------------------------------
__global__ void __launch_bounds__(256) gemm_kernel(
    const float* __restrict__ state, const float* __restrict__ action,
    const float* __restrict__ embed, const float* __restrict__ W1,
    const float* __restrict__ b1)
{
    const int slot = blockIdx.y;
    const int x    = blockIdx.x;
    int colbase, kbase, kend;
    if (slot < 2) { colbase = (x >> 1) * 32; kbase = (x & 1) * 256; kend = kbase + 256; }
    else          { if (x >= 32) return; colbase = x * 32; kbase = 0; kend = 512; }

    const float* W = W1 + slot * DIMK * HD;

    __shared__ float Xs[64][132];

    const int tid = threadIdx.x;
    const int tx  = tid & 15;
    const int ty  = tid >> 4;

    float acc[4][2] = {};

    for (int kt = kbase; kt < kend; kt += 128) {
        for (int lin = tid; lin < 64 * 32; lin += 256) {
            int row = lin >> 5;
            int q   = lin & 31;
            int gc  = kt + q * 4;
            float4 v;
            if (slot < 2) {
                v = *reinterpret_cast<const float4*>(embed + row * DIMK + gc);
            } else {
                float4 s4 = *reinterpret_cast<const float4*>(state  + row * DIMK + gc);
                float4 a4 = *reinterpret_cast<const float4*>(action + row * DIMK + gc);
                v = make_float4(s4.x + a4.x, s4.y + a4.y, s4.z + a4.z, s4.w + a4.w);
            }
            *reinterpret_cast<float4*>(&Xs[row][q * 4]) = v;
        }
        __syncthreads();

        #pragma unroll 4
        for (int k = 0; k < 128; k++) {
            float2 w = *reinterpret_cast<const float2*>(W + (kt + k) * HD + colbase + 2 * tx);
            #pragma unroll
            for (int r = 0; r < 4; r++) {
                float xv = Xs[ty + 16 * r][k];
                acc[r][0] = fmaf(xv, w.x, acc[r][0]);
                acc[r][1] = fmaf(xv, w.y, acc[r][1]);
            }
        }
        __syncthreads();
    }

    #pragma unroll
    for (int r = 0; r < 4; r++) {
        int row = ty + 16 * r;
        int c0  = colbase + 2 * tx;
        if (slot == 0) {
            float v0 = acc[r][0], v1 = acc[r][1];
            if (kbase == 0) { v0 += b1[c0]; v1 += b1[c0 + 1]; }
            float* dst = (kbase == 0) ? g_causA : g_causB;
            dst[row * HD + c0]     = v0;
            dst[row * HD + c0 + 1] = v1;
        } else if (slot == 1) {
            float* dst = (kbase == 0) ? g_effA : g_effB;
            dst[row * HD + c0]     = acc[r][0];
            dst[row * HD + c0 + 1] = acc[r][1];
        } else {
            g_ctxT[c0 * 64 + row]       = acc[r][0];
            g_ctxT[(c0 + 1) * 64 + row] = acc[r][1];
        }
    }
}

// ---------------------------------------------------------------------------
// f32x2 packed helpers (Blackwell; ptxas will not auto-fuse these from C++)
// ---------------------------------------------------------------------------
__device__ __forceinline__ ull pack2(float a, float b) {
    ull r;
    asm("mov.b64 %0, {%1, %2};" : "=l"(r)
        : "r"(__float_as_uint(a)), "r"(__float_as_uint(b)));
    return r;
}
__device__ __forceinline__ void unpack2(ull v, float& a, float& b) {
    unsigned int x, y;
    asm("mov.b64 {%0, %1}, %2;" : "=r"(x), "=r"(y) : "l"(v));
    a = __uint_as_float(x); b = __uint_as_float(y);
}
__device__ __forceinline__ ull add2(ull a, ull b) {
    ull r; asm("add.rn.f32x2 %0, %1, %2;" : "=l"(r) : "l"(a), "l"(b)); return r;
}
__device__ __forceinline__ ull mul2(ull a, ull b) {
    ull r; asm("mul.rn.f32x2 %0, %1, %2;" : "=l"(r) : "l"(a), "l"(b)); return r;
}
__device__ __forceinline__ ull fma2(ull a, ull b, ull c) {
    ull r; asm("fma.rn.f32x2 %0, %1, %2, %3;" : "=l"(r) : "l"(a), "l"(b), "l"(c)); return r;
}
__device__ __forceinline__ float tanh_ap(float x) {
    float r; asm("tanh.approx.f32 %0, %1;" : "=f"(r) : "f"(x)); return r;
}

// ---------------------------------------------------------------------------
// Phase 2: scores[i,j] = mean_b sigmoid( sum_h gelu(ctx+caus+eff)*W2 + b2 )
// tanh-GELU: gelu(x) = 0.5x * (1 + tanh(x*(c0 + c1*x^2))), tanh via MUFU.
// Block = 128 threads (4 warps), 2x2 (i,j) tile, 1 pair/warp.
// Lane owns batches (2*lane, 2*lane+1) -> f32x2 packed math throughout.
// grid = 1024 blocks; smem 56KB -> 4 blocks/SM.
// ---------------------------------------------------------------------------
__global__ void __launch_bounds__(128) score_kernel(
    const float* __restrict__ W2, const float* __restrict__ b2,
    float* __restrict__ out)
{
    extern __shared__ float sm[];
    float* caus_s = sm;             // 2048 (2 rows)
    float* eff_s  = sm + 2048;      // 2048 (2 rows)
    float* w2p    = sm + 4096;      // 2048 (1024 pairs, pre-halved & duplicated)
    float* ctx_s  = sm + 6144;      // 8192 (128 h x 64 b)

    const int tid = threadIdx.x;
    const int i0  = (blockIdx.x >> 5) * 2;
    const int j0  = (blockIdx.x & 31) * 2;

    for (int lin = tid; lin < 2048; lin += 128) {
        int r = lin >> 10, c = lin & 1023;
        caus_s[lin] = g_causA[(i0 + r) * HD + c] + g_causB[(i0 + r) * HD + c];
        eff_s [lin] = g_effA [(j0 + r) * HD + c] + g_effB [(j0 + r) * HD + c];
    }
    for (int lin = tid; lin < 1024; lin += 128) {
        float v = 0.5f * W2[lin];
        w2p[2 * lin]     = v;
        w2p[2 * lin + 1] = v;
    }

    const int w    = tid >> 5;
    const int lane = tid & 31;
    const float* cs = caus_s + (w >> 1) * 1024;
    const float* es = eff_s  + (w & 1) * 1024;
    const ull*  ctxp = reinterpret_cast<const ull*>(ctx_s);

    const ull C0 = pack2(0.7978845608f, 0.7978845608f);
    const ull C1 = pack2(0.0356774081f, 0.0356774081f);
    ull accL = pack2(0.f, 0.f);   // sum of 0.5*x*w2
    ull accT = pack2(0.f, 0.f);   // sum of 0.5*x*w2*tanh

    for (int ht = 0; ht < HD; ht += 128) {
        __syncthreads();
        for (int lin = tid * 4; lin < 128 * 64; lin += 128 * 4) {
            *reinterpret_cast<float4*>(ctx_s + lin) =
                *reinterpret_cast<const float4*>(g_ctxT + ht * 64 + lin);
        }
        __syncthreads();

        const float* w2row = w2p + 2 * ht;
        #pragma unroll 4
        for (int k = 0; k < 128; k += 4) {
            float4 cv = *reinterpret_cast<const float4*>(cs + ht + k);
            float4 ev = *reinterpret_cast<const float4*>(es + ht + k);
            float ce[4] = {cv.x + ev.x, cv.y + ev.y, cv.z + ev.z, cv.w + ev.w};
            #pragma unroll
            for (int q = 0; q < 4; q++) {
                ull ce2 = pack2(ce[q], ce[q]);
                ull hw2 = *reinterpret_cast<const ull*>(w2row + 2 * (k + q));
                ull c2  = ctxp[(k + q) * 32 + lane];
                ull x2  = add2(ce2, c2);
                ull u2  = mul2(x2, x2);
                ull p2  = fma2(u2, C1, C0);
                ull in2 = mul2(x2, p2);
                float ia, ib; unpack2(in2, ia, ib);
                ull t2  = pack2(tanh_ap(ia), tanh_ap(ib));
                ull xw2 = mul2(x2, hw2);
                accL = add2(accL, xw2);
                accT = fma2(xw2, t2, accT);
            }
        }
    }

    ull acc = add2(accL, accT);
    float a0, a1; unpack2(acc, a0, a1);
    float bb = b2[0];
    float s = 1.0f / (1.0f + expf(-(a0 + bb)))
            + 1.0f / (1.0f + expf(-(a1 + bb)));
    #pragma unroll
    for (int off = 16; off; off >>= 1)
        s += __shfl_down_sync(0xffffffffu, s, off);
    if (lane == 0)
        out[(i0 + (w >> 1)) * 64 + (j0 + (w & 1))] = s * (1.0f / 64.0f);
}

// ---------------------------------------------------------------------------
extern "C" void kernel_launch(void* const* d_in, const int* in_sizes, int n_in,
                              void* d_out, int out_size)
{
    const float* state  = (const float*)d_in[0];
    const float* action = (const float*)d_in[1];
    const float* embed  = (const float*)d_in[2];
    const float* W1     = (const float*)d_in[3];
    const float* b1     = (const float*)d_in[4];
    const float* W2     = (const float*)d_in[5];
    const float* b2     = (const float*)d_in[6];
    float* out = (float*)d_out;

    dim3 g1(64, 3);
    gemm_kernel<<<g1, 256>>>(state, action, embed, W1, b1);

    const int smem = (2048 + 2048 + 2048 + 8192) * sizeof(float); // 57344 B
    cudaFuncSetAttribute(score_kernel, cudaFuncAttributeMaxDynamicSharedMemorySize, smem);
    score_kernel<<<1024, 128, smem>>>(W2, b2, out);
}

// round 3
// speedup vs baseline: 2.4993x; 1.1068x over previous
#include <cuda_runtime.h>
#include <math.h>

#define DIMK 512
#define HD   1024

typedef unsigned long long ull;

// Scratch (device globals). k-split partial results (A: k<256, B: k>=256).
__device__ __align__(16) float g_causA[64 * HD];
__device__ __align__(16) float g_causB[64 * HD];
__device__ __align__(16) float g_effA [64 * HD];
__device__ __align__(16) float g_effB [64 * HD];
__device__ __align__(16) float g_ctxTA[HD * 64];   // transposed [h][b], k-half A
__device__ __align__(16) float g_ctxTB[HD * 64];   // transposed [h][b], k-half B

// ---------------------------------------------------------------------------
// Phase 1: three 64x512 @ 512x1024 GEMMs, all k-split in halves.
// grid = (64, 3): x>>1 = col-tile (32 cols), x&1 = k-half (256 k).
// block = 256 threads; each thread 4 rows x 2 cols. 192 equal-work blocks.
// ---------------------------------------------------------------------------
__global__ void __launch_bounds__(256) gemm_kernel(
    const float* __restrict__ state, const float* __restrict__ action,
    const float* __restrict__ embed, const float* __restrict__ W1,
    const float* __restrict__ b1)
{
    const int slot    = blockIdx.y;
    const int colbase = (blockIdx.x >> 1) * 32;
    const int kbase   = (blockIdx.x & 1) * 256;

    const float* W = W1 + slot * DIMK * HD;

    __shared__ float Xs[64][132];

    const int tid = threadIdx.x;
    const int tx  = tid & 15;
    const int ty  = tid >> 4;

    float acc[4][2] = {};

    for (int kt = kbase; kt < kbase + 256; kt += 128) {
        for (int lin = tid; lin < 64 * 32; lin += 256) {
            int row = lin >> 5;
            int q   = lin & 31;
            int gc  = kt + q * 4;
            float4 v;
            if (slot < 2) {
                v = *reinterpret_cast<const float4*>(embed + row * DIMK + gc);
            } else {
                float4 s4 = *reinterpret_cast<const float4*>(state  + row * DIMK + gc);
                float4 a4 = *reinterpret_cast<const float4*>(action + row * DIMK + gc);
                v = make_float4(s4.x + a4.x, s4.y + a4.y, s4.z + a4.z, s4.w + a4.w);
            }
            *reinterpret_cast<float4*>(&Xs[row][q * 4]) = v;
        }
        __syncthreads();

        #pragma unroll 4
        for (int k = 0; k < 128; k++) {
            float2 w = *reinterpret_cast<const float2*>(W + (kt + k) * HD + colbase + 2 * tx);
            #pragma unroll
            for (int r = 0; r < 4; r++) {
                float xv = Xs[ty + 16 * r][k];
                acc[r][0] = fmaf(xv, w.x, acc[r][0]);
                acc[r][1] = fmaf(xv, w.y, acc[r][1]);
            }
        }
        __syncthreads();
    }

    const int isA = (kbase == 0);
    #pragma unroll
    for (int r = 0; r < 4; r++) {
        int row = ty + 16 * r;
        int c0  = colbase + 2 * tx;
        if (slot == 0) {
            float v0 = acc[r][0], v1 = acc[r][1];
            if (isA) { v0 += b1[c0]; v1 += b1[c0 + 1]; }
            float* dst = isA ? g_causA : g_causB;
            dst[row * HD + c0]     = v0;
            dst[row * HD + c0 + 1] = v1;
        } else if (slot == 1) {
            float* dst = isA ? g_effA : g_effB;
            dst[row * HD + c0]     = acc[r][0];
            dst[row * HD + c0 + 1] = acc[r][1];
        } else {
            float* dst = isA ? g_ctxTA : g_ctxTB;
            dst[c0 * 64 + row]       = acc[r][0];
            dst[(c0 + 1) * 64 + row] = acc[r][1];
        }
    }
}

// ---------------------------------------------------------------------------
// f32x2 packed helpers
// ---------------------------------------------------------------------------
__device__ __forceinline__ ull pack2(float a, float b) {
    ull r;
    asm("mov.b64 %0, {%1, %2};" : "=l"(r)
        : "r"(__float_as_uint(a)), "r"(__float_as_uint(b)));
    return r;
}
__device__ __forceinline__ void unpack2(ull v, float& a, float& b) {
    unsigned int x, y;
    asm("mov.b64 {%0, %1}, %2;" : "=r"(x), "=r"(y) : "l"(v));
    a = __uint_as_float(x); b = __uint_as_float(y);
}
__device__ __forceinline__ ull add2(ull a, ull b) {
    ull r; asm("add.rn.f32x2 %0, %1, %2;" : "=l"(r) : "l"(a), "l"(b)); return r;
}
__device__ __forceinline__ ull mul2(ull a, ull b) {
    ull r; asm("mul.rn.f32x2 %0, %1, %2;" : "=l"(r) : "l"(a), "l"(b)); return r;
}
__device__ __forceinline__ ull fma2(ull a, ull b, ull c) {
    ull r; asm("fma.rn.f32x2 %0, %1, %2, %3;" : "=l"(r) : "l"(a), "l"(b), "l"(c)); return r;
}
__device__ __forceinline__ float tanh_ap(float x) {
    float r; asm("tanh.approx.f32 %0, %1;" : "=f"(r) : "f"(x)); return r;
}

// ---------------------------------------------------------------------------
// Phase 2: scores[i,j] = mean_b sigmoid( sum_h gelu(ctx+caus+eff)*W2 + b2 )
// Block = 256 threads (8 warps) = 2i x 4j pair tile, 1 pair/warp.
// Lane owns batches (2*lane, 2*lane+1), f32x2 packed math, tanh via MUFU.
// ctx staged in 64-h tiles (16KB); smem total 48KB -> 4 blocks/SM = 32 warps.
// grid = 512 blocks <= 592 concurrent -> single wave.
// ---------------------------------------------------------------------------
__global__ void __launch_bounds__(256) score_kernel(
    const float* __restrict__ W2, const float* __restrict__ b2,
    float* __restrict__ out)
{
    extern __shared__ float sm[];
    float* caus_s = sm;              // 2 * 1024
    float* eff_s  = sm + 2048;       // 4 * 1024
    float* w2p    = sm + 6144;       // 2048 (1024 pairs, pre-halved, duplicated)
    float* ctx_s  = sm + 8192;       // 64 * 64

    const int tid = threadIdx.x;
    const int i0  = (blockIdx.x >> 4) * 2;   // 32 i-tiles
    const int j0  = (blockIdx.x & 15) * 4;   // 16 j-tiles

    for (int lin = tid; lin < 2048; lin += 256) {
        int r = lin >> 10, c = lin & 1023;
        caus_s[lin] = g_causA[(i0 + r) * HD + c] + g_causB[(i0 + r) * HD + c];
    }
    for (int lin = tid; lin < 4096; lin += 256) {
        int r = lin >> 10, c = lin & 1023;
        eff_s[lin]  = g_effA[(j0 + r) * HD + c] + g_effB[(j0 + r) * HD + c];
    }
    for (int lin = tid; lin < 1024; lin += 256) {
        float v = 0.5f * W2[lin];
        w2p[2 * lin]     = v;
        w2p[2 * lin + 1] = v;
    }

    const int w    = tid >> 5;
    const int lane = tid & 31;
    const int wi   = w >> 2, wj = w & 3;
    const float* cs = caus_s + wi * 1024;
    const float* es = eff_s  + wj * 1024;
    const ull*  ctxp = reinterpret_cast<const ull*>(ctx_s);

    const ull C0 = pack2(0.7978845608f, 0.7978845608f);
    const ull C1 = pack2(0.0356774081f, 0.0356774081f);
    ull accL = pack2(0.f, 0.f);
    ull accT = pack2(0.f, 0.f);

    for (int ht = 0; ht < HD; ht += 64) {
        __syncthreads();   // covers initial staging on first iter
        // stage ctx tile: 64h x 64b, summing the two k-half partials
        for (int lin = tid * 4; lin < 64 * 64; lin += 256 * 4) {
            float4 a4 = *reinterpret_cast<const float4*>(g_ctxTA + ht * 64 + lin);
            float4 b4 = *reinterpret_cast<const float4*>(g_ctxTB + ht * 64 + lin);
            *reinterpret_cast<float4*>(ctx_s + lin) =
                make_float4(a4.x + b4.x, a4.y + b4.y, a4.z + b4.z, a4.w + b4.w);
        }
        __syncthreads();

        const float* w2row = w2p + 2 * ht;
        #pragma unroll 4
        for (int k = 0; k < 64; k += 4) {
            float4 cv = *reinterpret_cast<const float4*>(cs + ht + k);
            float4 ev = *reinterpret_cast<const float4*>(es + ht + k);
            float ce[4] = {cv.x + ev.x, cv.y + ev.y, cv.z + ev.z, cv.w + ev.w};
            #pragma unroll
            for (int q = 0; q < 4; q++) {
                ull ce2 = pack2(ce[q], ce[q]);
                ull hw2 = *reinterpret_cast<const ull*>(w2row + 2 * (k + q));
                ull c2  = ctxp[(k + q) * 32 + lane];
                ull x2  = add2(ce2, c2);
                ull u2  = mul2(x2, x2);
                ull p2  = fma2(u2, C1, C0);
                ull in2 = mul2(x2, p2);
                float ia, ib; unpack2(in2, ia, ib);
                ull t2  = pack2(tanh_ap(ia), tanh_ap(ib));
                ull xw2 = mul2(x2, hw2);
                accL = add2(accL, xw2);
                accT = fma2(xw2, t2, accT);
            }
        }
    }

    ull acc = add2(accL, accT);
    float a0, a1; unpack2(acc, a0, a1);
    float bb = b2[0];
    float s = 1.0f / (1.0f + expf(-(a0 + bb)))
            + 1.0f / (1.0f + expf(-(a1 + bb)));
    #pragma unroll
    for (int off = 16; off; off >>= 1)
        s += __shfl_down_sync(0xffffffffu, s, off);
    if (lane == 0)
        out[(i0 + wi) * 64 + (j0 + wj)] = s * (1.0f / 64.0f);
}

// ---------------------------------------------------------------------------
extern "C" void kernel_launch(void* const* d_in, const int* in_sizes, int n_in,
                              void* d_out, int out_size)
{
    const float* state  = (const float*)d_in[0];
    const float* action = (const float*)d_in[1];
    const float* embed  = (const float*)d_in[2];
    const float* W1     = (const float*)d_in[3];
    const float* b1     = (const float*)d_in[4];
    const float* W2     = (const float*)d_in[5];
    const float* b2     = (const float*)d_in[6];
    float* out = (float*)d_out;

    dim3 g1(64, 3);
    gemm_kernel<<<g1, 256>>>(state, action, embed, W1, b1);

    const int smem = (2048 + 4096 + 2048 + 4096) * sizeof(float); // 49152 B
    cudaFuncSetAttribute(score_kernel, cudaFuncAttributeMaxDynamicSharedMemorySize, smem);
    score_kernel<<<512, 256, smem>>>(W2, b2, out);
}